// round 1
// baseline (speedup 1.0000x reference)
#include <cuda_runtime.h>
#include <math.h>
#include <stdint.h>

// ---------------- static scratch (no allocations allowed) ----------------
#define D_CAP 2048
#define N_CAP 6144
#define C_CAP 1024
#define SCAP  1536   // max members per class we can rank (actual avg ~5)

__device__ float g_rnorm[N_CAP];                       // 1/||support row||
__device__ float g_logits[(size_t)N_CAP * C_CAP];      // [N, C]
__device__ float g_ent[N_CAP];
__device__ int   g_yhat[N_CAP];
__device__ float g_wT[(size_t)C_CAP * D_CAP];          // [C, D] transposed weights

// ---------------- row norms of the virtual support set [W; z] ----------------
__global__ void row_rnorm_kernel(const float* __restrict__ z, const float* __restrict__ W,
                                 int Bn, int Cn, int Dn) {
    int i = blockIdx.x;
    const float* src = (i < Cn) ? (W + (size_t)i * Dn) : (z + (size_t)(i - Cn) * Dn);
    float ss = 0.f;
    for (int d = threadIdx.x; d < Dn; d += blockDim.x) {
        float v = src[d];
        ss += v * v;
    }
    __shared__ float red[256];
    red[threadIdx.x] = ss;
    __syncthreads();
    for (int s = 128; s > 0; s >>= 1) {
        if (threadIdx.x < s) red[threadIdx.x] += red[threadIdx.x + s];
        __syncthreads();
    }
    if (threadIdx.x == 0) g_rnorm[i] = 1.f / fmaxf(sqrtf(red[0]), 1e-12f);
}

// ---------------- fp32 SGEMM  C[M,Nc] = A[M,Kd] * B[Nc,Kd]^T ----------------
// 64x64 tile, BK=16, 256 threads, 4x4 per-thread microtile.
__global__ __launch_bounds__(256) void sgemm_abt(const float* __restrict__ A,
                                                 const float* __restrict__ B,
                                                 float* __restrict__ Cm,
                                                 int M, int Nc, int Kd) {
    __shared__ float As[16][68];   // 68-float row stride: 272B = 17*16B, float4-aligned
    __shared__ float Bs[16][68];

    const int bm = blockIdx.y * 64;
    const int bn = blockIdx.x * 64;
    const int tid = threadIdx.x;
    const int tn = tid & 15;       // 0..15 -> 4 output cols
    const int tm = tid >> 4;       // 0..15 -> 4 output rows

    const int lrow = tid >> 2;         // 0..63 loader row
    const int lcol = (tid & 3) * 4;    // 0,4,8,12 loader k-offset

    const bool aval = (bm + lrow) < M;
    const bool bval = (bn + lrow) < Nc;
    const float* Aptr = A + (size_t)(bm + lrow) * Kd + lcol;
    const float* Bptr = B + (size_t)(bn + lrow) * Kd + lcol;

    float acc[4][4];
#pragma unroll
    for (int i = 0; i < 4; i++)
#pragma unroll
        for (int j = 0; j < 4; j++) acc[i][j] = 0.f;

    for (int k0 = 0; k0 < Kd; k0 += 16) {
        float4 av = aval ? *(const float4*)(Aptr + k0) : make_float4(0.f, 0.f, 0.f, 0.f);
        float4 bv = bval ? *(const float4*)(Bptr + k0) : make_float4(0.f, 0.f, 0.f, 0.f);
        __syncthreads();
        As[lcol + 0][lrow] = av.x; As[lcol + 1][lrow] = av.y;
        As[lcol + 2][lrow] = av.z; As[lcol + 3][lrow] = av.w;
        Bs[lcol + 0][lrow] = bv.x; Bs[lcol + 1][lrow] = bv.y;
        Bs[lcol + 2][lrow] = bv.z; Bs[lcol + 3][lrow] = bv.w;
        __syncthreads();
#pragma unroll
        for (int k = 0; k < 16; k++) {
            float4 a4 = *(const float4*)(&As[k][tm * 4]);
            float4 b4 = *(const float4*)(&Bs[k][tn * 4]);
            float avv[4] = {a4.x, a4.y, a4.z, a4.w};
            float bvv[4] = {b4.x, b4.y, b4.z, b4.w};
#pragma unroll
            for (int i = 0; i < 4; i++)
#pragma unroll
                for (int j = 0; j < 4; j++) acc[i][j] += avv[i] * bvv[j];
        }
    }

#pragma unroll
    for (int i = 0; i < 4; i++) {
        int r = bm + tm * 4 + i;
        if (r < M) {
#pragma unroll
            for (int j = 0; j < 4; j++) {
                int cc = bn + tn * 4 + j;
                if (cc < Nc) Cm[(size_t)r * Nc + cc] = acc[i][j];
            }
        }
    }
}

// ---------------- per-row entropy + argmax over C columns ----------------
__global__ void ent_argmax_kernel(const float* __restrict__ L, int Nrows, int Cn) {
    int row = blockIdx.x;
    const float* Lr = L + (size_t)row * Cn;
    int t = threadIdx.x;

    float bm = -1e38f;
    int bi = 0x7fffffff;
    for (int j = t; j < Cn; j += 256) {
        float v = Lr[j];
        if (v > bm || (v == bm && j < bi)) { bm = v; bi = j; }
    }
    __shared__ float sv[256];
    __shared__ float sw[256];
    __shared__ int si[256];
    sv[t] = bm; si[t] = bi;
    __syncthreads();
    for (int s = 128; s > 0; s >>= 1) {
        if (t < s) {
            float v2 = sv[t + s]; int i2 = si[t + s];
            if (v2 > sv[t] || (v2 == sv[t] && i2 < si[t])) { sv[t] = v2; si[t] = i2; }
        }
        __syncthreads();
    }
    float m = sv[0];
    int best = si[0];
    __syncthreads();

    float s0 = 0.f, s1 = 0.f;
    for (int j = t; j < Cn; j += 256) {
        float v = Lr[j];
        float e = expf(v - m);
        s0 += e;
        s1 += v * e;
    }
    sv[t] = s0; sw[t] = s1;
    __syncthreads();
    for (int s = 128; s > 0; s >>= 1) {
        if (t < s) { sv[t] += sv[t + s]; sw[t] += sw[t + s]; }
        __syncthreads();
    }
    if (t == 0) {
        float S0 = sv[0], S1 = sw[0];
        float lse = m + logf(S0);
        g_ent[row] = lse - S1 / S0;   // -(sum p*logp) = lse - E[logit]
        g_yhat[row] = best;
    }
}

// ---------------- per-class select (top-filter_K lowest entropy) + prototype ----------------
__global__ void build_weights_kernel(const float* __restrict__ z, const float* __restrict__ W,
                                     int Nrows, int Bn, int Cn, int Dn,
                                     const int* __restrict__ pK) {
    const int c = blockIdx.x;
    const int t = threadIdx.x;      // 256 threads
    const int K = *pK;

    __shared__ int s_idx[SCAP];
    __shared__ float s_ent[SCAP];
    __shared__ unsigned char s_sel[SCAP];
    __shared__ int s_wcnt[8];
    __shared__ int s_cnt;
    __shared__ float s_scale;
    __shared__ float red[256];

    if (t == 0) s_cnt = 0;
    __syncthreads();

    // deterministic, index-ordered compaction of members of class c
    const int w = t >> 5, lane = t & 31;
    for (int base = 0; base < Nrows; base += 256) {
        int i = base + t;
        bool f = (i < Nrows) && (g_yhat[i] == c);
        unsigned mask = __ballot_sync(0xffffffffu, f);
        if (lane == 0) s_wcnt[w] = __popc(mask);
        __syncthreads();
        int off = s_cnt;
        for (int ww = 0; ww < w; ww++) off += s_wcnt[ww];
        if (f) {
            int pos = off + __popc(mask & ((1u << lane) - 1u));
            if (pos < SCAP) { s_idx[pos] = i; s_ent[pos] = g_ent[i]; }
        }
        __syncthreads();
        if (t == 0) {
            int tot = 0;
            for (int ww = 0; ww < 8; ww++) tot += s_wcnt[ww];
            s_cnt += tot;
        }
        __syncthreads();
    }

    const int cnt = s_cnt;
    const int listn = (cnt < SCAP) ? cnt : SCAP;

    // selection: all if cnt<=K, else exact rank with (ent, idx) tie-break
    if (cnt <= K) {
        for (int m = t; m < listn; m += 256) s_sel[m] = 1;
    } else {
        for (int m = t; m < listn; m += 256) {
            float e = s_ent[m];
            int id = s_idx[m];
            int r = 0;
            for (int j = 0; j < listn; j++) {
                float ej = s_ent[j];
                r += (ej < e) || (ej == e && s_idx[j] < id);
            }
            s_sel[m] = (r < K) ? 1 : 0;
        }
    }
    __syncthreads();

    // accumulate normalized selected supports: wcol[d] = sum_i S[i][d]/||S[i]||
    const int DPT = Dn >> 8;   // Dn/256 (Dn=2048 -> 8)
    float acc[8];
#pragma unroll
    for (int j = 0; j < 8; j++) acc[j] = 0.f;

    for (int m = 0; m < listn; m++) {
        if (!s_sel[m]) continue;
        int i = s_idx[m];
        float rs = g_rnorm[i];
        const float* Sp = (i < Cn) ? (W + (size_t)i * Dn) : (z + (size_t)(i - Cn) * Dn);
#pragma unroll
        for (int j = 0; j < 8; j++) {
            if (j < DPT) acc[j] += Sp[t + (j << 8)] * rs;
        }
    }

    // column normalize
    float ss = 0.f;
#pragma unroll
    for (int j = 0; j < 8; j++)
        if (j < DPT) ss += acc[j] * acc[j];
    red[t] = ss;
    __syncthreads();
    for (int s = 128; s > 0; s >>= 1) {
        if (t < s) red[t] += red[t + s];
        __syncthreads();
    }
    if (t == 0) s_scale = 1.f / fmaxf(sqrtf(red[0]), 1e-12f);
    __syncthreads();
    float sc = s_scale;
#pragma unroll
    for (int j = 0; j < 8; j++)
        if (j < DPT) g_wT[(size_t)c * Dn + t + (j << 8)] = acc[j] * sc;
}

// ---------------- launch ----------------
extern "C" void kernel_launch(void* const* d_in, const int* in_sizes, int n_in,
                              void* d_out, int out_size) {
    const float* z = (const float*)d_in[0];
    const float* W = (const float*)d_in[1];
    const int* pK = (const int*)d_in[2];

    // B*D, C*D, B*C known -> D = sqrt(in0*in1/out)
    double dd = sqrt((double)in_sizes[0] * (double)in_sizes[1] / (double)out_size);
    int Dn = (int)(dd + 0.5);
    int Bn = in_sizes[0] / Dn;
    int Cn = in_sizes[1] / Dn;
    int Nn = Bn + Cn;

    float *Lp, *Wp;
    cudaGetSymbolAddress((void**)&Lp, g_logits);
    cudaGetSymbolAddress((void**)&Wp, g_wT);

    // 1. support row norms
    row_rnorm_kernel<<<Nn, 256>>>(z, W, Bn, Cn, Dn);

    // 2. logits: rows [0,C) = W@W^T ; rows [C,N) = z@W^T
    {
        dim3 gw((Cn + 63) / 64, (Cn + 63) / 64);
        sgemm_abt<<<gw, 256>>>(W, W, Lp, Cn, Cn, Dn);
        dim3 gz((Cn + 63) / 64, (Bn + 63) / 64);
        sgemm_abt<<<gz, 256>>>(z, W, Lp + (size_t)Cn * Cn, Bn, Cn, Dn);
    }

    // 3. entropy + argmax per support row
    ent_argmax_kernel<<<Nn, 256>>>(Lp, Nn, Cn);

    // 4. per-class selection + normalized prototype weights
    build_weights_kernel<<<Cn, 256>>>(z, W, Nn, Bn, Cn, Dn, pK);

    // 5. out = z @ weights  (weights stored transposed [C, D])
    {
        dim3 go((Cn + 63) / 64, (Bn + 63) / 64);
        sgemm_abt<<<go, 256>>>(z, Wp, (float*)d_out, Bn, Cn, Dn);
    }
}

// round 5
// speedup vs baseline: 2.3128x; 2.3128x over previous
#include <cuda_runtime.h>
#include <cuda_bf16.h>
#include <math.h>
#include <stdint.h>

// ---------------- problem caps (fixed shapes: B=4096, D=2048, C=1000) ----------------
#define D_CAP   2048
#define KEXT_CAP (3 * D_CAP)           // 6144 (split-bf16 K extension)
#define MP_CAP  5120                   // ceil(5096/128)*128
#define CP_CAP  1024                   // ceil(1000/128)*128
#define N_CAP   6144
#define SCAP    1536

// ---------------- static scratch ----------------
__device__ __nv_bfloat16 g_Sext[(size_t)MP_CAP * KEXT_CAP];   // [hi|lo|hi] supports [W;z]
__device__ __nv_bfloat16 g_Bext[(size_t)CP_CAP * KEXT_CAP];   // [hi|hi|lo] of W
__device__ __nv_bfloat16 g_wText[(size_t)CP_CAP * KEXT_CAP];  // [hi|hi|lo] of weights^T
__device__ float g_logits[(size_t)MP_CAP * CP_CAP];           // ld = CP_CAP
__device__ float g_rnorm[N_CAP];
__device__ float g_ent[N_CAP];
__device__ int   g_yhat[N_CAP];
__device__ float g_wT[(size_t)CP_CAP * D_CAP];                // fp32 [C, D]

// ---------------- helpers ----------------
__device__ __forceinline__ uint32_t smem_u32(const void* p) {
    uint32_t a;
    asm("{ .reg .u64 t; cvta.to.shared.u64 t, %1; cvt.u32.u64 %0, t; }" : "=r"(a) : "l"(p));
    return a;
}
__device__ __forceinline__ uint32_t sw64(uint32_t off) { return off ^ ((off >> 3) & 0x30); }

#define CP_ASYNC16(dst, src) \
    asm volatile("cp.async.cg.shared.global [%0], [%1], 16;" :: "r"(dst), "l"(src))
#define CP_COMMIT() asm volatile("cp.async.commit_group;" ::: "memory")
#define CP_WAIT(n)  asm volatile("cp.async.wait_group %0;" :: "n"(n) : "memory")

__device__ __forceinline__ void ldsm4(uint32_t* r, uint32_t addr) {
    asm volatile("ldmatrix.sync.aligned.m8n8.x4.shared.b16 {%0,%1,%2,%3}, [%4];"
                 : "=r"(r[0]), "=r"(r[1]), "=r"(r[2]), "=r"(r[3]) : "r"(addr));
}
__device__ __forceinline__ void mma16816(float* c, const uint32_t* a, const uint32_t* b) {
    asm volatile("mma.sync.aligned.m16n8k16.row.col.f32.bf16.bf16.f32 "
                 "{%0,%1,%2,%3}, {%4,%5,%6,%7}, {%8,%9}, {%0,%1,%2,%3};"
                 : "+f"(c[0]), "+f"(c[1]), "+f"(c[2]), "+f"(c[3])
                 : "r"(a[0]), "r"(a[1]), "r"(a[2]), "r"(a[3]), "r"(b[0]), "r"(b[1]));
}

// ---------------- split-bf16 operand build ----------------
__global__ void conv_supports_kernel(const float* __restrict__ z, const float* __restrict__ W,
                                     int Bn, int Cn, int Nn, int Dn, int Kext) {
    int row = blockIdx.x;
    const float* src = (row < Cn) ? (W + (size_t)row * Dn)
                                  : ((row < Nn) ? (z + (size_t)(row - Cn) * Dn) : nullptr);
    __nv_bfloat16* Sr = g_Sext + (size_t)row * Kext;
    __nv_bfloat16* Br = (row < CP_CAP) ? (g_Bext + (size_t)row * Kext) : nullptr;
    for (int d = threadIdx.x; d < Dn; d += blockDim.x) {
        float x = src ? src[d] : 0.f;
        __nv_bfloat16 hi = __float2bfloat16(x);
        __nv_bfloat16 lo = __float2bfloat16(x - __bfloat162float(hi));
        Sr[d] = hi; Sr[Dn + d] = lo; Sr[2 * Dn + d] = hi;
        if (Br) {
            bool v = (row < Cn);
            __nv_bfloat16 zb = __float2bfloat16(0.f);
            Br[d] = v ? hi : zb; Br[Dn + d] = v ? hi : zb; Br[2 * Dn + d] = v ? lo : zb;
        }
    }
}

__global__ void conv_w_kernel(int Cn, int Dn, int Kext) {
    int row = blockIdx.x;
    const float* src = (row < Cn) ? (g_wT + (size_t)row * Dn) : nullptr;
    __nv_bfloat16* Br = g_wText + (size_t)row * Kext;
    for (int d = threadIdx.x; d < Dn; d += blockDim.x) {
        float x = src ? src[d] : 0.f;
        __nv_bfloat16 hi = __float2bfloat16(x);
        __nv_bfloat16 lo = __float2bfloat16(x - __bfloat162float(hi));
        Br[d] = hi; Br[Dn + d] = hi; Br[2 * Dn + d] = lo;
    }
}

// ---------------- bf16 HMMA GEMM: C[M,N] = A[M,K] * B[N,K]^T ----------------
// 128x128 tile, BK=32, 3-stage cp.async, SW64 smem, 8 warps (2x4), warp tile 64x32.
#define STAGE_BYTES 16384    // A 8KB + B 8KB
#define STAGES 3

__global__ __launch_bounds__(256, 2)
void gemm_mma_kernel(const __nv_bfloat16* __restrict__ A, const __nv_bfloat16* __restrict__ B,
                     float* __restrict__ C, int ldc, int nvalid, int Kext) {
    extern __shared__ char smem[];
    const uint32_t sb = smem_u32(smem);
    const int tid = threadIdx.x;
    const int wid = tid >> 5, lane = tid & 31;
    const int wm = wid >> 2, wn = wid & 3;

    const size_t tm = (size_t)blockIdx.y * 128;
    const size_t tn = (size_t)blockIdx.x * 128;
    const __nv_bfloat16* Ab = A + tm * Kext;
    const __nv_bfloat16* Bb = B + tn * Kext;
    const int niter = Kext >> 5;

    // loader: thread t covers rows {t>>2, t>>2 + 64}, 16B chunk t&3, for A and B.
    // 256 threads * 4 * 16B = 16KB per stage = full coverage of both 8KB tiles.
    const int lr = tid >> 2, lc = tid & 3;
    const uint32_t a_st = sw64((uint32_t)(lr * 64 + lc * 16));   // +4096 swizzle-invariant
    const uint32_t b_st = 8192 + a_st;
    const char* a_src0 = (const char*)(Ab + (size_t)lr * Kext + lc * 8);
    const char* a_src1 = (const char*)(Ab + (size_t)(lr + 64) * Kext + lc * 8);
    const char* b_src0 = (const char*)(Bb + (size_t)lr * Kext + lc * 8);
    const char* b_src1 = (const char*)(Bb + (size_t)(lr + 64) * Kext + lc * 8);

#define LOADST(it, buf) do {                                        \
        uint32_t _o = sb + (uint32_t)(buf) * STAGE_BYTES;           \
        size_t _k = (size_t)(it) * 64;                              \
        CP_ASYNC16(_o + a_st,        a_src0 + _k);                  \
        CP_ASYNC16(_o + a_st + 4096, a_src1 + _k);                  \
        CP_ASYNC16(_o + b_st,        b_src0 + _k);                  \
        CP_ASYNC16(_o + b_st + 4096, b_src1 + _k);                  \
        CP_COMMIT();                                                \
    } while (0)

    // ldmatrix per-lane base addresses (ks=0, mt=0/ntp=0)
    const int mat = lane >> 3, rin = lane & 7;
    const uint32_t a_lm = sw64((uint32_t)((wm * 64 + (mat & 1) * 8 + rin) * 64 + (mat >> 1) * 16));
    const uint32_t b_lm = 8192 + sw64((uint32_t)((wn * 32 + (mat >> 1) * 8 + rin) * 64 + (mat & 1) * 16));

    float acc[4][4][4];
#pragma unroll
    for (int i = 0; i < 4; i++)
#pragma unroll
        for (int j = 0; j < 4; j++)
#pragma unroll
            for (int k = 0; k < 4; k++) acc[i][j][k] = 0.f;

    LOADST(0, 0);
    LOADST(1, 1);

    for (int it = 0; it < niter; it++) {
        CP_WAIT(1);
        __syncthreads();
        {
            const uint32_t base = sb + (uint32_t)(it % STAGES) * STAGE_BYTES;
#pragma unroll
            for (int ks = 0; ks < 2; ks++) {
                uint32_t ar[4][4], br[4][2];
#pragma unroll
                for (int mt = 0; mt < 4; mt++)
                    ldsm4(ar[mt], base + ((a_lm + mt * 1024u) ^ (ks << 5)));
#pragma unroll
                for (int ntp = 0; ntp < 2; ntp++) {
                    uint32_t r[4];
                    ldsm4(r, base + ((b_lm + ntp * 1024u) ^ (ks << 5)));
                    br[2 * ntp][0] = r[0]; br[2 * ntp][1] = r[1];
                    br[2 * ntp + 1][0] = r[2]; br[2 * ntp + 1][1] = r[3];
                }
#pragma unroll
                for (int mt = 0; mt < 4; mt++)
#pragma unroll
                    for (int nt = 0; nt < 4; nt++)
                        mma16816(acc[mt][nt], ar[mt], br[nt]);
            }
        }
        __syncthreads();
        if (it + 2 < niter) LOADST(it + 2, (it + 2) % STAGES);
        else CP_COMMIT();
    }

    // epilogue
    const int r0 = lane >> 2, c0 = (lane & 3) * 2;
#pragma unroll
    for (int mt = 0; mt < 4; mt++) {
#pragma unroll
        for (int nt = 0; nt < 4; nt++) {
            size_t row = tm + wm * 64 + mt * 16 + r0;
            int col = (int)tn + wn * 32 + nt * 8 + c0;
            if (col < nvalid) {
                float2 v0 = make_float2(acc[mt][nt][0], acc[mt][nt][1]);
                float2 v1 = make_float2(acc[mt][nt][2], acc[mt][nt][3]);
                *(float2*)&C[row * (size_t)ldc + col] = v0;
                *(float2*)&C[(row + 8) * (size_t)ldc + col] = v1;
            }
        }
    }
#undef LOADST
}

// ---------------- support row norms (fp32, exact) ----------------
__global__ void row_rnorm_kernel(const float* __restrict__ z, const float* __restrict__ W,
                                 int Bn, int Cn, int Dn) {
    int i = blockIdx.x;
    const float* src = (i < Cn) ? (W + (size_t)i * Dn) : (z + (size_t)(i - Cn) * Dn);
    float ss = 0.f;
    for (int d = threadIdx.x; d < Dn; d += blockDim.x) { float v = src[d]; ss += v * v; }
    __shared__ float red[256];
    red[threadIdx.x] = ss;
    __syncthreads();
    for (int s = 128; s > 0; s >>= 1) {
        if (threadIdx.x < s) red[threadIdx.x] += red[threadIdx.x + s];
        __syncthreads();
    }
    if (threadIdx.x == 0) g_rnorm[i] = 1.f / fmaxf(sqrtf(red[0]), 1e-12f);
}

// ---------------- per-row entropy + argmax ----------------
__global__ void ent_argmax_kernel(const float* __restrict__ L, int Nrows, int Cn, int ldl) {
    int row = blockIdx.x;
    const float* Lr = L + (size_t)row * ldl;
    int t = threadIdx.x;

    float bm = -1e38f;
    int bi = 0x7fffffff;
    for (int j = t; j < Cn; j += 256) {
        float v = Lr[j];
        if (v > bm || (v == bm && j < bi)) { bm = v; bi = j; }
    }
    __shared__ float sv[256];
    __shared__ float sw[256];
    __shared__ int si[256];
    sv[t] = bm; si[t] = bi;
    __syncthreads();
    for (int s = 128; s > 0; s >>= 1) {
        if (t < s) {
            float v2 = sv[t + s]; int i2 = si[t + s];
            if (v2 > sv[t] || (v2 == sv[t] && i2 < si[t])) { sv[t] = v2; si[t] = i2; }
        }
        __syncthreads();
    }
    float m = sv[0];
    int best = si[0];
    __syncthreads();

    float s0 = 0.f, s1 = 0.f;
    for (int j = t; j < Cn; j += 256) {
        float v = Lr[j];
        float e = expf(v - m);
        s0 += e; s1 += v * e;
    }
    sv[t] = s0; sw[t] = s1;
    __syncthreads();
    for (int s = 128; s > 0; s >>= 1) {
        if (t < s) { sv[t] += sv[t + s]; sw[t] += sw[t + s]; }
        __syncthreads();
    }
    if (t == 0) {
        float S0 = sv[0], S1 = sw[0];
        g_ent[row] = m + logf(S0) - S1 / S0;
        g_yhat[row] = best;
    }
}

// ---------------- per-class select + normalized prototype (fp32 exact) ----------------
__global__ void build_weights_kernel(const float* __restrict__ z, const float* __restrict__ W,
                                     int Nrows, int Bn, int Cn, int Dn,
                                     const int* __restrict__ pK) {
    const int c = blockIdx.x;
    const int t = threadIdx.x;
    const int K = *pK;

    __shared__ int s_idx[SCAP];
    __shared__ float s_ent[SCAP];
    __shared__ unsigned char s_sel[SCAP];
    __shared__ int s_wcnt[8];
    __shared__ int s_cnt;
    __shared__ float s_scale;
    __shared__ float red[256];

    if (t == 0) s_cnt = 0;
    __syncthreads();

    const int w = t >> 5, lane = t & 31;
    for (int base = 0; base < Nrows; base += 256) {
        int i = base + t;
        bool f = (i < Nrows) && (g_yhat[i] == c);
        unsigned mask = __ballot_sync(0xffffffffu, f);
        if (lane == 0) s_wcnt[w] = __popc(mask);
        __syncthreads();
        int off = s_cnt;
        for (int ww = 0; ww < w; ww++) off += s_wcnt[ww];
        if (f) {
            int pos = off + __popc(mask & ((1u << lane) - 1u));
            if (pos < SCAP) { s_idx[pos] = i; s_ent[pos] = g_ent[i]; }
        }
        __syncthreads();
        if (t == 0) {
            int tot = 0;
            for (int ww = 0; ww < 8; ww++) tot += s_wcnt[ww];
            s_cnt += tot;
        }
        __syncthreads();
    }

    const int cnt = s_cnt;
    const int listn = (cnt < SCAP) ? cnt : SCAP;

    if (cnt <= K) {
        for (int m = t; m < listn; m += 256) s_sel[m] = 1;
    } else {
        for (int m = t; m < listn; m += 256) {
            float e = s_ent[m];
            int id = s_idx[m];
            int r = 0;
            for (int j = 0; j < listn; j++) {
                float ej = s_ent[j];
                r += (ej < e) || (ej == e && s_idx[j] < id);
            }
            s_sel[m] = (r < K) ? 1 : 0;
        }
    }
    __syncthreads();

    const int DPT = Dn >> 8;
    float acc[8];
#pragma unroll
    for (int j = 0; j < 8; j++) acc[j] = 0.f;

    for (int m = 0; m < listn; m++) {
        if (!s_sel[m]) continue;
        int i = s_idx[m];
        float rs = g_rnorm[i];
        const float* Sp = (i < Cn) ? (W + (size_t)i * Dn) : (z + (size_t)(i - Cn) * Dn);
#pragma unroll
        for (int j = 0; j < 8; j++)
            if (j < DPT) acc[j] += Sp[t + (j << 8)] * rs;
    }

    float ss = 0.f;
#pragma unroll
    for (int j = 0; j < 8; j++)
        if (j < DPT) ss += acc[j] * acc[j];
    red[t] = ss;
    __syncthreads();
    for (int s = 128; s > 0; s >>= 1) {
        if (t < s) red[t] += red[t + s];
        __syncthreads();
    }
    if (t == 0) s_scale = 1.f / fmaxf(sqrtf(red[0]), 1e-12f);
    __syncthreads();
    float sc = s_scale;
#pragma unroll
    for (int j = 0; j < 8; j++)
        if (j < DPT) g_wT[(size_t)c * Dn + t + (j << 8)] = acc[j] * sc;
}

// ---------------- launch ----------------
extern "C" void kernel_launch(void* const* d_in, const int* in_sizes, int n_in,
                              void* d_out, int out_size) {
    const float* z = (const float*)d_in[0];
    const float* W = (const float*)d_in[1];
    const int* pK = (const int*)d_in[2];

    double dd = sqrt((double)in_sizes[0] * (double)in_sizes[1] / (double)out_size);
    int Dn = (int)(dd + 0.5);
    int Bn = in_sizes[0] / Dn;
    int Cn = in_sizes[1] / Dn;
    int Nn = Bn + Cn;
    int Kext = 3 * Dn;
    int Mp = ((Nn + 127) / 128) * 128;
    int Cp = ((Cn + 127) / 128) * 128;

    __nv_bfloat16 *Sp, *Bp, *Wp;
    float* Lp;
    cudaGetSymbolAddress((void**)&Sp, g_Sext);
    cudaGetSymbolAddress((void**)&Bp, g_Bext);
    cudaGetSymbolAddress((void**)&Wp, g_wText);
    cudaGetSymbolAddress((void**)&Lp, g_logits);

    cudaFuncSetAttribute(gemm_mma_kernel, cudaFuncAttributeMaxDynamicSharedMemorySize,
                         STAGES * STAGE_BYTES);

    // 1. split-bf16 operands + row norms
    conv_supports_kernel<<<Mp, 256>>>(z, W, Bn, Cn, Nn, Dn, Kext);
    row_rnorm_kernel<<<Nn, 256>>>(z, W, Bn, Cn, Dn);

    // 2. logits = [W;z] @ W^T  (M=5120 padded, N=1024 padded)
    {
        dim3 g(Cp / 128, Mp / 128);
        gemm_mma_kernel<<<g, 256, STAGES * STAGE_BYTES>>>(Sp, Bp, Lp, CP_CAP, Cn, Kext);
    }

    // 3. entropy + argmax
    ent_argmax_kernel<<<Nn, 256>>>(Lp, Nn, Cn, CP_CAP);

    // 4. per-class selection + prototypes
    build_weights_kernel<<<Cn, 256>>>(z, W, Nn, Bn, Cn, Dn, pK);

    // 5. weights -> split-bf16, then out = z @ weights
    conv_w_kernel<<<Cp, 256>>>(Cn, Dn, Kext);
    {
        dim3 g(Cp / 128, Bn / 128);
        gemm_mma_kernel<<<g, 256, STAGES * STAGE_BYTES>>>(Sp + (size_t)Cn * Kext, Wp,
                                                          (float*)d_out, Cn, Cn, Kext);
    }
}

// round 6
// speedup vs baseline: 2.5120x; 1.0862x over previous
#include <cuda_runtime.h>
#include <cuda_bf16.h>
#include <math.h>
#include <stdint.h>

// ---------------- problem caps (fixed shapes: B=4096, D=2048, C=1000) ----------------
#define D_CAP   2048
#define KEXT_CAP (3 * D_CAP)           // 6144 (split-bf16 K extension)
#define MP_CAP  5120                   // ceil(5096/128)*128
#define CP_CAP  1024                   // ceil(1000/128)*128
#define N_CAP   6144
#define SCAP    1536

// ---------------- static scratch ----------------
__device__ __nv_bfloat16 g_Sext[(size_t)MP_CAP * KEXT_CAP];   // [hi|lo|hi] supports [W;z]
__device__ __nv_bfloat16 g_Bext[(size_t)CP_CAP * KEXT_CAP];   // [hi|hi|lo] of W
__device__ __nv_bfloat16 g_wText[(size_t)CP_CAP * KEXT_CAP];  // [hi|hi|lo] of weights^T
__device__ float g_logits[(size_t)MP_CAP * CP_CAP];           // ld = CP_CAP
__device__ float g_rnorm[N_CAP];
__device__ float g_ent[N_CAP];
__device__ int   g_yhat[N_CAP];
__device__ float g_wT[(size_t)CP_CAP * D_CAP];                // fp32 [C, D]

// ---------------- helpers ----------------
__device__ __forceinline__ uint32_t smem_u32(const void* p) {
    uint32_t a;
    asm("{ .reg .u64 t; cvta.to.shared.u64 t, %1; cvt.u32.u64 %0, t; }" : "=r"(a) : "l"(p));
    return a;
}
__device__ __forceinline__ uint32_t sw64(uint32_t off) { return off ^ ((off >> 3) & 0x30); }

#define CP_ASYNC16(dst, src) \
    asm volatile("cp.async.cg.shared.global [%0], [%1], 16;" :: "r"(dst), "l"(src))
#define CP_COMMIT() asm volatile("cp.async.commit_group;" ::: "memory")
#define CP_WAIT(n)  asm volatile("cp.async.wait_group %0;" :: "n"(n) : "memory")

__device__ __forceinline__ void ldsm4(uint32_t* r, uint32_t addr) {
    asm volatile("ldmatrix.sync.aligned.m8n8.x4.shared.b16 {%0,%1,%2,%3}, [%4];"
                 : "=r"(r[0]), "=r"(r[1]), "=r"(r[2]), "=r"(r[3]) : "r"(addr));
}
__device__ __forceinline__ void mma16816(float* c, const uint32_t* a, const uint32_t* b) {
    asm volatile("mma.sync.aligned.m16n8k16.row.col.f32.bf16.bf16.f32 "
                 "{%0,%1,%2,%3}, {%4,%5,%6,%7}, {%8,%9}, {%0,%1,%2,%3};"
                 : "+f"(c[0]), "+f"(c[1]), "+f"(c[2]), "+f"(c[3])
                 : "r"(a[0]), "r"(a[1]), "r"(a[2]), "r"(a[3]), "r"(b[0]), "r"(b[1]));
}

// ---------------- split-bf16 operand build + fused row norms ----------------
__global__ void conv_supports_kernel(const float* __restrict__ z, const float* __restrict__ W,
                                     int Bn, int Cn, int Nn, int Dn, int Kext) {
    int row = blockIdx.x;
    const float* src = (row < Cn) ? (W + (size_t)row * Dn)
                                  : ((row < Nn) ? (z + (size_t)(row - Cn) * Dn) : nullptr);
    __nv_bfloat16* Sr = g_Sext + (size_t)row * Kext;
    __nv_bfloat16* Br = (row < CP_CAP) ? (g_Bext + (size_t)row * Kext) : nullptr;
    float ss = 0.f;
    for (int d = threadIdx.x; d < Dn; d += blockDim.x) {
        float x = src ? src[d] : 0.f;
        ss += x * x;
        __nv_bfloat16 hi = __float2bfloat16(x);
        __nv_bfloat16 lo = __float2bfloat16(x - __bfloat162float(hi));
        Sr[d] = hi; Sr[Dn + d] = lo; Sr[2 * Dn + d] = hi;
        if (Br) {
            bool v = (row < Cn);
            __nv_bfloat16 zb = __float2bfloat16(0.f);
            Br[d] = v ? hi : zb; Br[Dn + d] = v ? hi : zb; Br[2 * Dn + d] = v ? lo : zb;
        }
    }
    // fused row norm (rows < Nn)
    __shared__ float red[256];
    red[threadIdx.x] = ss;
    __syncthreads();
    for (int s = 128; s > 0; s >>= 1) {
        if (threadIdx.x < s) red[threadIdx.x] += red[threadIdx.x + s];
        __syncthreads();
    }
    if (threadIdx.x == 0 && row < Nn) g_rnorm[row] = 1.f / fmaxf(sqrtf(red[0]), 1e-12f);
}

__global__ void conv_w_kernel(int Cn, int Dn, int Kext) {
    int row = blockIdx.x;
    const float* src = (row < Cn) ? (g_wT + (size_t)row * Dn) : nullptr;
    __nv_bfloat16* Br = g_wText + (size_t)row * Kext;
    for (int d = threadIdx.x; d < Dn; d += blockDim.x) {
        float x = src ? src[d] : 0.f;
        __nv_bfloat16 hi = __float2bfloat16(x);
        __nv_bfloat16 lo = __float2bfloat16(x - __bfloat162float(hi));
        Br[d] = hi; Br[Dn + d] = hi; Br[2 * Dn + d] = lo;
    }
}

// ---------------- bf16 HMMA GEMM: C[M,N] = A[M,K] * B[N,K]^T ----------------
// 128x128 tile, BK=32, 4-stage cp.async (prefetch distance 3, ONE sync/iter),
// SW64 smem, 8 warps (2x4), warp tile 64x32.
#define STAGE_BYTES 16384    // A 8KB + B 8KB
#define STAGES 4

__global__ __launch_bounds__(256, 2)
void gemm_mma_kernel(const __nv_bfloat16* __restrict__ A, const __nv_bfloat16* __restrict__ B,
                     float* __restrict__ C, int ldc, int nvalid, int Kext) {
    extern __shared__ char smem[];
    const uint32_t sb = smem_u32(smem);
    const int tid = threadIdx.x;
    const int wid = tid >> 5, lane = tid & 31;
    const int wm = wid >> 2, wn = wid & 3;

    const size_t tm = (size_t)blockIdx.y * 128;
    const size_t tn = (size_t)blockIdx.x * 128;
    const __nv_bfloat16* Ab = A + tm * Kext;
    const __nv_bfloat16* Bb = B + tn * Kext;
    const int niter = Kext >> 5;

    // loader: thread t covers rows {t>>2, t>>2 + 64}, 16B chunk t&3, for A and B.
    const int lr = tid >> 2, lc = tid & 3;
    const uint32_t a_st = sw64((uint32_t)(lr * 64 + lc * 16));   // +4096 swizzle-invariant
    const uint32_t b_st = 8192 + a_st;
    const char* a_src0 = (const char*)(Ab + (size_t)lr * Kext + lc * 8);
    const char* a_src1 = (const char*)(Ab + (size_t)(lr + 64) * Kext + lc * 8);
    const char* b_src0 = (const char*)(Bb + (size_t)lr * Kext + lc * 8);
    const char* b_src1 = (const char*)(Bb + (size_t)(lr + 64) * Kext + lc * 8);

#define LOADST(it, buf) do {                                        \
        uint32_t _o = sb + (uint32_t)(buf) * STAGE_BYTES;           \
        size_t _k = (size_t)(it) * 64;                              \
        CP_ASYNC16(_o + a_st,        a_src0 + _k);                  \
        CP_ASYNC16(_o + a_st + 4096, a_src1 + _k);                  \
        CP_ASYNC16(_o + b_st,        b_src0 + _k);                  \
        CP_ASYNC16(_o + b_st + 4096, b_src1 + _k);                  \
        CP_COMMIT();                                                \
    } while (0)

    // ldmatrix per-lane base addresses (ks=0, mt=0/ntp=0)
    const int mat = lane >> 3, rin = lane & 7;
    const uint32_t a_lm = sw64((uint32_t)((wm * 64 + (mat & 1) * 8 + rin) * 64 + (mat >> 1) * 16));
    const uint32_t b_lm = 8192 + sw64((uint32_t)((wn * 32 + (mat >> 1) * 8 + rin) * 64 + (mat & 1) * 16));

    float acc[4][4][4];
#pragma unroll
    for (int i = 0; i < 4; i++)
#pragma unroll
        for (int j = 0; j < 4; j++)
#pragma unroll
            for (int k = 0; k < 4; k++) acc[i][j][k] = 0.f;

    LOADST(0, 0);
    LOADST(1, 1);
    LOADST(2, 2);

    for (int it = 0; it < niter; it++) {
        CP_WAIT(2);            // stage it resident
        __syncthreads();       // (a) stage it visible to all  (b) stage (it-1) fully consumed
        if (it + 3 < niter) LOADST(it + 3, (it + 3) & 3);   // overwrite stage (it-1)%4
        else CP_COMMIT();      // keep group accounting uniform
        {
            const uint32_t base = sb + (uint32_t)(it & 3) * STAGE_BYTES;
#pragma unroll
            for (int ks = 0; ks < 2; ks++) {
                uint32_t ar[4][4], br[4][2];
#pragma unroll
                for (int mt = 0; mt < 4; mt++)
                    ldsm4(ar[mt], base + ((a_lm + mt * 1024u) ^ (ks << 5)));
#pragma unroll
                for (int ntp = 0; ntp < 2; ntp++) {
                    uint32_t r[4];
                    ldsm4(r, base + ((b_lm + ntp * 1024u) ^ (ks << 5)));
                    br[2 * ntp][0] = r[0]; br[2 * ntp][1] = r[1];
                    br[2 * ntp + 1][0] = r[2]; br[2 * ntp + 1][1] = r[3];
                }
#pragma unroll
                for (int mt = 0; mt < 4; mt++)
#pragma unroll
                    for (int nt = 0; nt < 4; nt++)
                        mma16816(acc[mt][nt], ar[mt], br[nt]);
            }
        }
    }

    // epilogue
    const int r0 = lane >> 2, c0 = (lane & 3) * 2;
#pragma unroll
    for (int mt = 0; mt < 4; mt++) {
#pragma unroll
        for (int nt = 0; nt < 4; nt++) {
            size_t row = tm + wm * 64 + mt * 16 + r0;
            int col = (int)tn + wn * 32 + nt * 8 + c0;
            if (col < nvalid) {
                float2 v0 = make_float2(acc[mt][nt][0], acc[mt][nt][1]);
                float2 v1 = make_float2(acc[mt][nt][2], acc[mt][nt][3]);
                *(float2*)&C[row * (size_t)ldc + col] = v0;
                *(float2*)&C[(row + 8) * (size_t)ldc + col] = v1;
            }
        }
    }
#undef LOADST
}

// ---------------- per-row entropy + argmax ----------------
__global__ void ent_argmax_kernel(const float* __restrict__ L, int Nrows, int Cn, int ldl) {
    int row = blockIdx.x;
    const float* Lr = L + (size_t)row * ldl;
    int t = threadIdx.x;

    float bm = -1e38f;
    int bi = 0x7fffffff;
    for (int j = t; j < Cn; j += 256) {
        float v = Lr[j];
        if (v > bm || (v == bm && j < bi)) { bm = v; bi = j; }
    }
    __shared__ float sv[256];
    __shared__ float sw[256];
    __shared__ int si[256];
    sv[t] = bm; si[t] = bi;
    __syncthreads();
    for (int s = 128; s > 0; s >>= 1) {
        if (t < s) {
            float v2 = sv[t + s]; int i2 = si[t + s];
            if (v2 > sv[t] || (v2 == sv[t] && i2 < si[t])) { sv[t] = v2; si[t] = i2; }
        }
        __syncthreads();
    }
    float m = sv[0];
    int best = si[0];
    __syncthreads();

    float s0 = 0.f, s1 = 0.f;
    for (int j = t; j < Cn; j += 256) {
        float v = Lr[j];
        float e = expf(v - m);
        s0 += e; s1 += v * e;
    }
    sv[t] = s0; sw[t] = s1;
    __syncthreads();
    for (int s = 128; s > 0; s >>= 1) {
        if (t < s) { sv[t] += sv[t + s]; sw[t] += sw[t + s]; }
        __syncthreads();
    }
    if (t == 0) {
        float S0 = sv[0], S1 = sw[0];
        g_ent[row] = m + logf(S0) - S1 / S0;
        g_yhat[row] = best;
    }
}

// ---------------- per-class select + normalized prototype (fp32 exact) ----------------
__global__ void build_weights_kernel(const float* __restrict__ z, const float* __restrict__ W,
                                     int Nrows, int Bn, int Cn, int Dn,
                                     const int* __restrict__ pK) {
    const int c = blockIdx.x;
    const int t = threadIdx.x;
    const int K = *pK;

    __shared__ int s_idx[SCAP];
    __shared__ float s_ent[SCAP];
    __shared__ unsigned char s_sel[SCAP];
    __shared__ int s_wcnt[8];
    __shared__ int s_cnt;
    __shared__ float s_scale;
    __shared__ float red[256];

    if (t == 0) s_cnt = 0;
    __syncthreads();

    const int w = t >> 5, lane = t & 31;
    for (int base = 0; base < Nrows; base += 256) {
        int i = base + t;
        bool f = (i < Nrows) && (g_yhat[i] == c);
        unsigned mask = __ballot_sync(0xffffffffu, f);
        if (lane == 0) s_wcnt[w] = __popc(mask);
        __syncthreads();
        int off = s_cnt;
        for (int ww = 0; ww < w; ww++) off += s_wcnt[ww];
        if (f) {
            int pos = off + __popc(mask & ((1u << lane) - 1u));
            if (pos < SCAP) { s_idx[pos] = i; s_ent[pos] = g_ent[i]; }
        }
        __syncthreads();
        if (t == 0) {
            int tot = 0;
            for (int ww = 0; ww < 8; ww++) tot += s_wcnt[ww];
            s_cnt += tot;
        }
        __syncthreads();
    }

    const int cnt = s_cnt;
    const int listn = (cnt < SCAP) ? cnt : SCAP;

    if (cnt <= K) {
        for (int m = t; m < listn; m += 256) s_sel[m] = 1;
    } else {
        for (int m = t; m < listn; m += 256) {
            float e = s_ent[m];
            int id = s_idx[m];
            int r = 0;
            for (int j = 0; j < listn; j++) {
                float ej = s_ent[j];
                r += (ej < e) || (ej == e && s_idx[j] < id);
            }
            s_sel[m] = (r < K) ? 1 : 0;
        }
    }
    __syncthreads();

    const int DPT = Dn >> 8;
    float acc[8];
#pragma unroll
    for (int j = 0; j < 8; j++) acc[j] = 0.f;

    for (int m = 0; m < listn; m++) {
        if (!s_sel[m]) continue;
        int i = s_idx[m];
        float rs = g_rnorm[i];
        const float* Sp = (i < Cn) ? (W + (size_t)i * Dn) : (z + (size_t)(i - Cn) * Dn);
#pragma unroll
        for (int j = 0; j < 8; j++)
            if (j < DPT) acc[j] += Sp[t + (j << 8)] * rs;
    }

    float ss = 0.f;
#pragma unroll
    for (int j = 0; j < 8; j++)
        if (j < DPT) ss += acc[j] * acc[j];
    red[t] = ss;
    __syncthreads();
    for (int s = 128; s > 0; s >>= 1) {
        if (t < s) red[t] += red[t + s];
        __syncthreads();
    }
    if (t == 0) s_scale = 1.f / fmaxf(sqrtf(red[0]), 1e-12f);
    __syncthreads();
    float sc = s_scale;
#pragma unroll
    for (int j = 0; j < 8; j++)
        if (j < DPT) g_wT[(size_t)c * Dn + t + (j << 8)] = acc[j] * sc;
}

// ---------------- launch ----------------
extern "C" void kernel_launch(void* const* d_in, const int* in_sizes, int n_in,
                              void* d_out, int out_size) {
    const float* z = (const float*)d_in[0];
    const float* W = (const float*)d_in[1];
    const int* pK = (const int*)d_in[2];

    double dd = sqrt((double)in_sizes[0] * (double)in_sizes[1] / (double)out_size);
    int Dn = (int)(dd + 0.5);
    int Bn = in_sizes[0] / Dn;
    int Cn = in_sizes[1] / Dn;
    int Nn = Bn + Cn;
    int Kext = 3 * Dn;
    int Mp = ((Nn + 127) / 128) * 128;
    int Cp = ((Cn + 127) / 128) * 128;

    __nv_bfloat16 *Sp, *Bp, *Wp;
    float* Lp;
    cudaGetSymbolAddress((void**)&Sp, g_Sext);
    cudaGetSymbolAddress((void**)&Bp, g_Bext);
    cudaGetSymbolAddress((void**)&Wp, g_wText);
    cudaGetSymbolAddress((void**)&Lp, g_logits);

    cudaFuncSetAttribute(gemm_mma_kernel, cudaFuncAttributeMaxDynamicSharedMemorySize,
                         STAGES * STAGE_BYTES);

    // 1. split-bf16 operands + fused row norms
    conv_supports_kernel<<<Mp, 256>>>(z, W, Bn, Cn, Nn, Dn, Kext);

    // 2. logits = [W;z] @ W^T
    {
        dim3 g(Cp / 128, Mp / 128);
        gemm_mma_kernel<<<g, 256, STAGES * STAGE_BYTES>>>(Sp, Bp, Lp, CP_CAP, Cn, Kext);
    }

    // 3. entropy + argmax
    ent_argmax_kernel<<<Nn, 256>>>(Lp, Nn, Cn, CP_CAP);

    // 4. per-class selection + prototypes
    build_weights_kernel<<<Cn, 256>>>(z, W, Nn, Bn, Cn, Dn, pK);

    // 5. weights -> split-bf16, then out = z @ weights
    conv_w_kernel<<<Cp, 256>>>(Cn, Dn, Kext);
    {
        dim3 g(Cp / 128, Bn / 128);
        gemm_mma_kernel<<<g, 256, STAGES * STAGE_BYTES>>>(Sp + (size_t)Cn * Kext, Wp,
                                                          (float*)d_out, Cn, Cn, Kext);
    }
}